// round 7
// baseline (speedup 1.0000x reference)
#include <cuda_runtime.h>
#include <math.h>

#define BD 8
#define HD 48
#define WD 48
#define CD 256
#define NPIX (BD * HD * WD)     // 18432
#define PIXB (HD * WD)          // 2304 pixels per batch
#define PLANE (HD * WD)         // 2304 elems per corr plane
#define PPB   32                // pixels per k_stats block
#define NBLK1 (NPIX / PPB)      // 576
#define BLKPB (NBLK1 / BD)      // 72 partial blocks per batch

// ---- scratch (device globals; no allocation allowed) ----
__device__ float g_cvraw[NPIX * 2];
__device__ float g_partials[NBLK1 * 2];        // (sum, sumsq) per k_stats block
__device__ float g_stats[BD * 2];              // (mu, inv_std) per batch

// ================= Kernel 1: MLP + mean output + cv raw + partial sums =================
// 256 threads (8 warps), 32 pixels/block. Lane (slot,o) computes the FULL 256-ch dot
// for (pixel slot, output o) -> zero shuffles. Weight chunks held in regs across 2 pairs.
__global__ __launch_bounds__(256) void k_stats(
    const float* __restrict__ x,
    const float* __restrict__ map_w, const float* __restrict__ map_b,
    const float* __restrict__ mean_w, const float* __restrict__ mean_b,
    const float* __restrict__ cov_w, const float* __restrict__ cov_b,
    float* __restrict__ out_mean)
{
    __shared__ float4 sw4[16 * 64];    // 16KB: map_w as float4 [o][c/4]
    __shared__ float4 sx4[PPB * 64];   // 32KB: x tile [p][c/4]
    const int tid = threadIdx.x;

    {
        const float4* wg = (const float4*)map_w;
        for (int i = tid; i < 16 * 64; i += 256) sw4[i] = wg[i];
        const float4* xg = (const float4*)x + (size_t)blockIdx.x * (PPB * 64);
        for (int i = tid; i < PPB * 64; i += 256) sx4[i] = xg[i];
    }
    __syncthreads();

    const int warp = tid >> 5, lane = tid & 31;
    const int o = lane & 15, slot = lane >> 4;
    const int px0 = warp * 4 + slot;        // pair-0 pixel (local)
    const int px1 = warp * 4 + 2 + slot;    // pair-1 pixel (local)

    float acc0 = 0.f, acc1 = 0.f;
#pragma unroll
    for (int ch = 0; ch < 16; ch++) {
        // weight chunk in registers, reused for both pixel pairs
        const float4 w0 = sw4[o * 64 + ch * 4 + 0];
        const float4 w1 = sw4[o * 64 + ch * 4 + 1];
        const float4 w2 = sw4[o * 64 + ch * 4 + 2];
        const float4 w3 = sw4[o * 64 + ch * 4 + 3];
        {
            const float4 a0 = sx4[px0 * 64 + ch * 4 + 0];
            const float4 a1 = sx4[px0 * 64 + ch * 4 + 1];
            const float4 a2 = sx4[px0 * 64 + ch * 4 + 2];
            const float4 a3 = sx4[px0 * 64 + ch * 4 + 3];
            acc0 = fmaf(a0.x, w0.x, acc0); acc0 = fmaf(a0.y, w0.y, acc0);
            acc0 = fmaf(a0.z, w0.z, acc0); acc0 = fmaf(a0.w, w0.w, acc0);
            acc0 = fmaf(a1.x, w1.x, acc0); acc0 = fmaf(a1.y, w1.y, acc0);
            acc0 = fmaf(a1.z, w1.z, acc0); acc0 = fmaf(a1.w, w1.w, acc0);
            acc0 = fmaf(a2.x, w2.x, acc0); acc0 = fmaf(a2.y, w2.y, acc0);
            acc0 = fmaf(a2.z, w2.z, acc0); acc0 = fmaf(a2.w, w2.w, acc0);
            acc0 = fmaf(a3.x, w3.x, acc0); acc0 = fmaf(a3.y, w3.y, acc0);
            acc0 = fmaf(a3.z, w3.z, acc0); acc0 = fmaf(a3.w, w3.w, acc0);
        }
        {
            const float4 a0 = sx4[px1 * 64 + ch * 4 + 0];
            const float4 a1 = sx4[px1 * 64 + ch * 4 + 1];
            const float4 a2 = sx4[px1 * 64 + ch * 4 + 2];
            const float4 a3 = sx4[px1 * 64 + ch * 4 + 3];
            acc1 = fmaf(a0.x, w0.x, acc1); acc1 = fmaf(a0.y, w0.y, acc1);
            acc1 = fmaf(a0.z, w0.z, acc1); acc1 = fmaf(a0.w, w0.w, acc1);
            acc1 = fmaf(a1.x, w1.x, acc1); acc1 = fmaf(a1.y, w1.y, acc1);
            acc1 = fmaf(a1.z, w1.z, acc1); acc1 = fmaf(a1.w, w1.w, acc1);
            acc1 = fmaf(a2.x, w2.x, acc1); acc1 = fmaf(a2.y, w2.y, acc1);
            acc1 = fmaf(a2.z, w2.z, acc1); acc1 = fmaf(a2.w, w2.w, acc1);
            acc1 = fmaf(a3.x, w3.x, acc1); acc1 = fmaf(a3.y, w3.y, acc1);
            acc1 = fmaf(a3.z, w3.z, acc1); acc1 = fmaf(a3.w, w3.w, acc1);
        }
    }
    const float mb = __ldg(&map_b[o]);
    const float t0 = tanhf(acc0 + mb);
    const float t1 = tanhf(acc1 + mb);

    // everyone is done reading sw4/sx4 -> safe to alias scratch over sx4
    __syncthreads();
    float* scratch = (float*)sx4;       // tts[32][17] then partials at +544/+576
    scratch[px0 * 17 + o] = t0;
    scratch[px1 * 17 + o] = t1;
    __syncthreads();

    // Head MLP: thread t (< 32) handles local pixel t (conflict-free: stride 17)
    if (tid < 32) {
        const int pid = blockIdx.x * PPB + tid;
        float m0 = __ldg(&mean_b[0]), m1 = __ldg(&mean_b[1]);
        float c0 = __ldg(&cov_b[0]),  c1 = __ldg(&cov_b[1]);
        const float* tt = scratch + tid * 17;
#pragma unroll
        for (int k = 0; k < 16; k++) {
            const float t = tt[k];
            m0 = fmaf(t, __ldg(&mean_w[k]),      m0);
            m1 = fmaf(t, __ldg(&mean_w[16 + k]), m1);
            c0 = fmaf(t, __ldg(&cov_w[k]),       c0);
            c1 = fmaf(t, __ldg(&cov_w[16 + k]),  c1);
        }
        const int hw = pid % PIXB;
        out_mean[pid * 2 + 0] = (float)(hw % WD) + m0;
        out_mean[pid * 2 + 1] = (float)(hw / WD) + m1;
        g_cvraw[pid * 2 + 0] = c0;
        g_cvraw[pid * 2 + 1] = c1;
        scratch[544 + tid] = c0 + c1;
        scratch[576 + tid] = c0 * c0 + c1 * c1;
    }
    __syncthreads();

    // deterministic fixed-order block partial (block never straddles batch: 2304%32==0)
    if (tid == 0) {
        float s = 0.f, q = 0.f;
#pragma unroll
        for (int i = 0; i < 32; i++) { s += scratch[544 + i]; q += scratch[576 + i]; }
        g_partials[blockIdx.x * 2 + 0] = s;
        g_partials[blockIdx.x * 2 + 1] = q;
    }
}

// ================= Kernel 2: per-batch reduction (deterministic tree) =================
__global__ __launch_bounds__(128) void k_reduce()
{
    __shared__ float s[128], q[128];
    const int b = blockIdx.x, t = threadIdx.x;
    float sv = 0.f, qv = 0.f;
    if (t < BLKPB) {
        sv = g_partials[(b * BLKPB + t) * 2 + 0];
        qv = g_partials[(b * BLKPB + t) * 2 + 1];
    }
    s[t] = sv; q[t] = qv;
    __syncthreads();
    for (int off = 64; off; off >>= 1) {
        if (t < off) { s[t] += s[t + off]; q[t] += q[t + off]; }
        __syncthreads();
    }
    if (t == 0) {
        const float n = (float)(PIXB * 2);     // 4608
        const float mu = s[0] / n;
        const float var = q[0] / n - mu * mu + 1e-5f;
        g_stats[b * 2 + 0] = mu;
        g_stats[b * 2 + 1] = rsqrtf(var);
    }
}

// ================= Kernel 3: HBM-bound apply (params computed inline) =================
__global__ __launch_bounds__(192) void k_apply(
    const float* __restrict__ corr, float* __restrict__ out,
    const float* __restrict__ mean_arr, float* __restrict__ out_det)
{
    const int pid = blockIdx.x;
    const int t = threadIdx.x;
    const float4* __restrict__ src = (const float4*)(corr + (size_t)pid * PLANE);
    float4* __restrict__ dst = (float4*)(out + (size_t)pid * PLANE);

    // issue the 3 streaming DRAM loads first (MLP=3), overlap with param math
    float4 c[3];
#pragma unroll
    for (int it = 0; it < 3; it++) c[it] = __ldcs(src + t + it * 192);

    // per-pixel params (redundant per thread; same-address loads broadcast, L2-hit)
    const int b = pid / PIXB;
    const float mu = g_stats[b * 2 + 0], istd = g_stats[b * 2 + 1];
    float c0 = (g_cvraw[pid * 2 + 0] - mu) * istd;
    float c1 = (g_cvraw[pid * 2 + 1] - mu) * istd;
    c0 = 5.f / (1.f + __expf(-c0)) + 0.05f;
    c1 = 5.f / (1.f + __expf(-c1)) + 0.05f;
    const float det = c0 * c1;
    if (t == 0) out_det[pid] = det;
    const float mx = __ldg(&mean_arr[pid * 2 + 0]);
    const float my = __ldg(&mean_arr[pid * 2 + 1]);
    const float ax = -0.5f / c0;
    const float ay = -0.5f / c1;
    const float s = rsqrtf(det) * (1.0f / 6.28f);

#pragma unroll
    for (int it = 0; it < 3; it++) {
        const int i = t + it * 192;          // float4 index in plane (0..575)
        const int h2 = i / 12;               // 12 float4s per 48-float row
        const float dy = (float)h2 - my;
        const bool iny = fabsf(dy) <= 6.0f;
        const float qy = ay * dy * dy;
        const float dx0 = (float)((i % 12) * 4) - mx;
        float4 v = c[it];
        {
            const float dx = dx0 + 0.f;
            if (iny && fabsf(dx) <= 6.0f)
                v.x = fmaf(v.x * s, __expf(fmaf(ax, dx * dx, qy)), v.x);
        }
        {
            const float dx = dx0 + 1.f;
            if (iny && fabsf(dx) <= 6.0f)
                v.y = fmaf(v.y * s, __expf(fmaf(ax, dx * dx, qy)), v.y);
        }
        {
            const float dx = dx0 + 2.f;
            if (iny && fabsf(dx) <= 6.0f)
                v.z = fmaf(v.z * s, __expf(fmaf(ax, dx * dx, qy)), v.z);
        }
        {
            const float dx = dx0 + 3.f;
            if (iny && fabsf(dx) <= 6.0f)
                v.w = fmaf(v.w * s, __expf(fmaf(ax, dx * dx, qy)), v.w);
        }
        __stcs(dst + i, v);
    }
}

// ======================================================================
extern "C" void kernel_launch(void* const* d_in, const int* in_sizes, int n_in,
                              void* d_out, int out_size)
{
    const float* x      = (const float*)d_in[0];
    const float* corr   = (const float*)d_in[1];
    const float* map_w  = (const float*)d_in[2];
    const float* map_b  = (const float*)d_in[3];
    const float* mean_w = (const float*)d_in[4];
    const float* mean_b = (const float*)d_in[5];
    const float* cov_w  = (const float*)d_in[6];
    const float* cov_b  = (const float*)d_in[7];

    float* out = (float*)d_out;
    // outputs concatenated flat: corr1 (b,h,w,h,w), mean (b,h,w,2), det (b,h*w)
    float* out_corr1 = out;
    float* out_mean  = out + (size_t)NPIX * PLANE;
    float* out_det   = out_mean + (size_t)NPIX * 2;

    k_stats<<<NBLK1, 256>>>(x, map_w, map_b, mean_w, mean_b, cov_w, cov_b, out_mean);
    k_reduce<<<BD, 128>>>();
    k_apply<<<NPIX, 192>>>(corr, out_corr1, out_mean, out_det);
}

// round 8
// speedup vs baseline: 1.1315x; 1.1315x over previous
#include <cuda_runtime.h>
#include <math.h>

#define BD 8
#define HD 48
#define WD 48
#define CD 256
#define NPIX (BD * HD * WD)     // 18432
#define PIXB (HD * WD)          // 2304 pixels per batch
#define PLANE (HD * WD)         // 2304 elems per corr plane
#define PPB   16                // pixels per k_stats block (8 warps x 2)
#define NBLK1 (NPIX / PPB)      // 1152
#define BLKPB (NBLK1 / BD)      // 144 partial blocks per batch

// ---- scratch (device globals; no allocation allowed) ----
__device__ float g_cvraw[NPIX * 2];
__device__ float g_partials[BD * BLKPB * 2];   // (sum, sumsq) per block
__device__ float g_stats[BD * 2];              // (mu, inv_std) per batch

// ================= Kernel 1: MLP + mean output + cv raw + partial sums =================
// (round-6 version: conflict-free lane-indexed weight loads, 21.4us measured; fully
//  hidden under the concurrent 48us corr copy, so no further tuning needed)
__global__ __launch_bounds__(256) void k_stats(
    const float* __restrict__ x,
    const float* __restrict__ map_w, const float* __restrict__ map_b,
    const float* __restrict__ mean_w, const float* __restrict__ mean_b,
    const float* __restrict__ cov_w, const float* __restrict__ cov_b,
    float* __restrict__ out_mean)
{
    __shared__ float4 sw4[16 * 64];   // map_w as float4 [o][c/4], 16KB
    __shared__ float red[PPB * 2];    // per-pixel (sum, sumsq)
    const int tid = threadIdx.x;
    {
        const float4* w4 = (const float4*)map_w;
        for (int i = tid; i < 16 * 64; i += 256) sw4[i] = w4[i];
    }
    __syncthreads();

    const int warp = tid >> 5, lane = tid & 31;
    const int pidA = blockIdx.x * PPB + warp * 2;   // pixel A (B = A+1)

    const float4* __restrict__ x4 = (const float4*)x;
    const float4 xA0 = x4[(size_t)pidA * 64 + lane];
    const float4 xA1 = x4[(size_t)pidA * 64 + 32 + lane];
    const float4 xB0 = x4[(size_t)(pidA + 1) * 64 + lane];
    const float4 xB1 = x4[(size_t)(pidA + 1) * 64 + 32 + lane];

    float acc[32];
#pragma unroll
    for (int o = 0; o < 16; o++) {
        const float4 w0 = sw4[o * 64 + lane];
        const float4 w1 = sw4[o * 64 + 32 + lane];
        float a = xA0.x * w0.x;
        a = fmaf(xA0.y, w0.y, a); a = fmaf(xA0.z, w0.z, a); a = fmaf(xA0.w, w0.w, a);
        a = fmaf(xA1.x, w1.x, a); a = fmaf(xA1.y, w1.y, a);
        a = fmaf(xA1.z, w1.z, a); a = fmaf(xA1.w, w1.w, a);
        float c = xB0.x * w0.x;
        c = fmaf(xB0.y, w0.y, c); c = fmaf(xB0.z, w0.z, c); c = fmaf(xB0.w, w0.w, c);
        c = fmaf(xB1.x, w1.x, c); c = fmaf(xB1.y, w1.y, c);
        c = fmaf(xB1.z, w1.z, c); c = fmaf(xB1.w, w1.w, c);
        acc[o] = a;
        acc[16 + o] = c;
    }

    // Multi-value butterfly: lane l ends holding the full sum of acc[l]
#pragma unroll
    for (int d = 16; d >= 1; d >>= 1) {
        const int half = d;
#pragma unroll
        for (int j = 0; j < 16; j++) {
            if (j < half) {
                float send = (lane & d) ? acc[j] : acc[j + half];
                float recv = __shfl_xor_sync(0xffffffffu, send, d);
                float mine = (lane & d) ? acc[j + half] : acc[j];
                acc[j] = mine + recv;
            }
        }
    }
    const int o = lane & 15;
    const float tt = tanhf(acc[0] + __ldg(&map_b[o]));

    float vals[4];
    vals[0] = tt * __ldg(&mean_w[o]);
    vals[1] = tt * __ldg(&mean_w[16 + o]);
    vals[2] = tt * __ldg(&cov_w[o]);
    vals[3] = tt * __ldg(&cov_w[16 + o]);
    {   // d=8: 4->2
        float send = (lane & 8) ? vals[0] : vals[2];
        float recv = __shfl_xor_sync(0xffffffffu, send, 8);
        vals[0] = ((lane & 8) ? vals[2] : vals[0]) + recv;
        send = (lane & 8) ? vals[1] : vals[3];
        recv = __shfl_xor_sync(0xffffffffu, send, 8);
        vals[1] = ((lane & 8) ? vals[3] : vals[1]) + recv;
    }
    {   // d=4: 2->1
        float send = (lane & 4) ? vals[0] : vals[1];
        float recv = __shfl_xor_sync(0xffffffffu, send, 4);
        vals[0] = ((lane & 4) ? vals[1] : vals[0]) + recv;
    }
    vals[0] += __shfl_xor_sync(0xffffffffu, vals[0], 2);
    vals[0] += __shfl_xor_sync(0xffffffffu, vals[0], 1);
    // quad q = (lane&15)>>2: q0=m0, q1=m1, q2=c0, q3=c1 (replicated x4)

    const int p = lane >> 4;
    const int pid = pidA + p;
    const int hl = lane & 15;
    const int q = hl >> 2;
    const int hw = pid % PIXB;
    const float r = vals[0];

    if (hl == 0) out_mean[pid * 2 + 0] = (float)(hw % WD) + __ldg(&mean_b[0]) + r;
    if (hl == 4) out_mean[pid * 2 + 1] = (float)(hw / WD) + __ldg(&mean_b[1]) + r;

    const float cb = r + __ldg(&cov_b[q & 1]);
    const float ex = __shfl_xor_sync(0xffffffffu, cb, 4);
    if (hl == 8)  g_cvraw[pid * 2 + 0] = cb;
    if (hl == 12) g_cvraw[pid * 2 + 1] = cb;
    if (hl == 8) {
        red[(warp * 2 + p) * 2 + 0] = cb + ex;
        red[(warp * 2 + p) * 2 + 1] = cb * cb + ex * ex;
    }
    __syncthreads();

    if (tid == 0) {
        float s = 0.f, qq = 0.f;
#pragma unroll
        for (int i = 0; i < PPB; i++) { s += red[i * 2]; qq += red[i * 2 + 1]; }
        const int b = blockIdx.x / BLKPB;
        const int blk = blockIdx.x % BLKPB;
        g_partials[(b * BLKPB + blk) * 2 + 0] = s;
        g_partials[(b * BLKPB + blk) * 2 + 1] = qq;
    }
}

// ================= Kernel 2: per-batch reduction (deterministic tree) =================
__global__ __launch_bounds__(256) void k_reduce()
{
    __shared__ float s[256], q[256];
    const int b = blockIdx.x, t = threadIdx.x;
    float sv = 0.f, qv = 0.f;
    if (t < BLKPB) {
        sv = g_partials[(b * BLKPB + t) * 2 + 0];
        qv = g_partials[(b * BLKPB + t) * 2 + 1];
    }
    s[t] = sv; q[t] = qv;
    __syncthreads();
    for (int off = 128; off; off >>= 1) {
        if (t < off) { s[t] += s[t + off]; q[t] += q[t + off]; }
        __syncthreads();
    }
    if (t == 0) {
        const float n = (float)(PIXB * 2);     // 4608
        const float mu = s[0] / n;
        const float var = q[0] / n - mu * mu + 1e-5f;
        g_stats[b * 2 + 0] = mu;
        g_stats[b * 2 + 1] = rsqrtf(var);
    }
}

// ================= Kernel 3: window-only update (out already holds corr copy) =====
// One warp per pixel. Touches exactly the cells where inwin is true:
// x in [ceil(mx-6), floor(mx+6)] ∩ [0,47]  ==  { x : |x-mx| <= 6 } for integer x.
__global__ __launch_bounds__(256) void k_win(
    const float* __restrict__ corr, float* __restrict__ out,
    const float* __restrict__ mean_arr, float* __restrict__ out_det)
{
    const int warp = threadIdx.x >> 5, lane = threadIdx.x & 31;
    const int pid = blockIdx.x * 8 + warp;

    // per-pixel params (broadcast loads, L2-hit)
    const int b = pid / PIXB;
    const float mu = g_stats[b * 2 + 0], istd = g_stats[b * 2 + 1];
    float c0 = (g_cvraw[pid * 2 + 0] - mu) * istd;
    float c1 = (g_cvraw[pid * 2 + 1] - mu) * istd;
    c0 = 5.f / (1.f + __expf(-c0)) + 0.05f;
    c1 = 5.f / (1.f + __expf(-c1)) + 0.05f;
    const float det = c0 * c1;
    if (lane == 0) out_det[pid] = det;
    const float mx = __ldg(&mean_arr[pid * 2 + 0]);
    const float my = __ldg(&mean_arr[pid * 2 + 1]);
    const float ax = -0.5f / c0;
    const float ay = -0.5f / c1;
    const float s = rsqrtf(det) * (1.0f / 6.28f);

    int x0 = max(0, (int)ceilf(mx - 6.0f));
    int x1 = min(WD - 1, (int)floorf(mx + 6.0f));
    int y0 = max(0, (int)ceilf(my - 6.0f));
    int y1 = min(HD - 1, (int)floorf(my + 6.0f));
    const int nx = x1 - x0 + 1;
    const int ny = y1 - y0 + 1;
    if (nx <= 0 || ny <= 0) return;
    const int n = nx * ny;

    const float* __restrict__ src = corr + (size_t)pid * PLANE;
    float* __restrict__ dst = out + (size_t)pid * PLANE;

    for (int i = lane; i < n; i += 32) {
        const int yy = y0 + i / nx;
        const int xx = x0 + i % nx;
        const float dx = (float)xx - mx;
        const float dy = (float)yy - my;
        const float e = __expf(fmaf(ax, dx * dx, ay * dy * dy));
        const float v = src[yy * WD + xx];
        dst[yy * WD + xx] = fmaf(v * s, e, v);
    }
}

// ======================================================================
extern "C" void kernel_launch(void* const* d_in, const int* in_sizes, int n_in,
                              void* d_out, int out_size)
{
    const float* x      = (const float*)d_in[0];
    const float* corr   = (const float*)d_in[1];
    const float* map_w  = (const float*)d_in[2];
    const float* map_b  = (const float*)d_in[3];
    const float* mean_w = (const float*)d_in[4];
    const float* mean_b = (const float*)d_in[5];
    const float* cov_w  = (const float*)d_in[6];
    const float* cov_b  = (const float*)d_in[7];

    float* out = (float*)d_out;
    // outputs concatenated flat: corr1 (b,h,w,h,w), mean (b,h,w,2), det (b,h*w)
    float* out_corr1 = out;
    float* out_mean  = out + (size_t)NPIX * PLANE;
    float* out_det   = out_mean + (size_t)NPIX * 2;

    // Fork: bulk corr->out copy runs concurrently with the stats pipeline.
    // (host-side stream/event creation only; intentionally not destroyed because
    //  capture is still active when this function returns)
    cudaStream_t s2;
    cudaStreamCreateWithFlags(&s2, cudaStreamNonBlocking);
    cudaEvent_t evFork, evCopy;
    cudaEventCreateWithFlags(&evFork, cudaEventDisableTiming);
    cudaEventCreateWithFlags(&evCopy, cudaEventDisableTiming);

    cudaEventRecord(evFork, 0);
    cudaStreamWaitEvent(s2, evFork, 0);
    cudaMemcpyAsync(out_corr1, corr, sizeof(float) * (size_t)NPIX * PLANE,
                    cudaMemcpyDeviceToDevice, s2);
    cudaEventRecord(evCopy, s2);

    k_stats<<<NBLK1, 256>>>(x, map_w, map_b, mean_w, mean_b, cov_w, cov_b, out_mean);
    k_reduce<<<BD, 256>>>();

    // Join: window update needs both the copy and the stats.
    cudaStreamWaitEvent(0, evCopy, 0);
    k_win<<<NPIX / 8, 256>>>(corr, out_corr1, out_mean, out_det);
}